// round 1
// baseline (speedup 1.0000x reference)
#include <cuda_runtime.h>
#include <math.h>

// Problem constants
constexpr int Bn = 8, Sn = 1024, Dn = 512, Hn = 8, HD = 64, Fn = 2048;
constexpr int Mtok = Bn * Sn; // 8192

// Scratch (static device globals; no runtime allocation)
__device__ float gQ [Mtok * Dn];
__device__ float gK [Mtok * Dn];
__device__ float gV [Mtok * Dn];
__device__ float gS [(size_t)Bn * Hn * Sn * Sn];   // 256 MB scores/attn (in place)
__device__ float gCtx[Mtok * Dn];
__device__ float gY [Mtok * Dn];
__device__ float gX1[Mtok * Dn];
__device__ float gH1[(size_t)Mtok * Fn];
__device__ float gY2[Mtok * Dn];

enum { EPI_NONE = 0, EPI_BIAS = 1, EPI_MISH = 2 };

__device__ __forceinline__ float mish_f(float v) {
    float sp = (v > 20.f) ? v : log1pf(expf(v));
    return v * tanhf(sp);
}

// ---------------------------------------------------------------------------
// Generic SGEMM: C = A @ B (+bias) (+mish).  BTRANS: B stored [N,K] (K-major).
// Tile 128x128, K-tile 8, 256 threads, 8x8 per-thread microtile.
// Batched over blockIdx.z with (b,h) = (z/Hdiv, z%Hdiv) stride decomposition.
// Assumes K % 8 == 0, N % 8 == 0, all leading dims % 4 == 0.
// ---------------------------------------------------------------------------
template <int EPI, bool BTRANS>
__global__ __launch_bounds__(256)
void sgemm(const float* __restrict__ Ag, const float* __restrict__ Bg,
           const float* __restrict__ bias, float* __restrict__ Cg,
           int M, int N, int K, int lda, int ldb, int ldc,
           long long sA_b, long long sA_h,
           long long sB_b, long long sB_h,
           long long sC_b, long long sC_h, int Hdiv)
{
    int z  = blockIdx.z;
    int bb = z / Hdiv, hh = z - bb * Hdiv;
    const float* A = Ag + (size_t)bb * sA_b + (size_t)hh * sA_h;
    const float* B = Bg + (size_t)bb * sB_b + (size_t)hh * sB_h;
    float*       C = Cg + (size_t)bb * sC_b + (size_t)hh * sC_h;

    __shared__ float As[8][128];
    __shared__ float Bs[8][128];

    int tid = threadIdx.x;
    int tx = tid & 15, ty = tid >> 4;
    int m0 = blockIdx.y * 128, n0 = blockIdx.x * 128;

    float acc[8][8];
#pragma unroll
    for (int i = 0; i < 8; i++)
#pragma unroll
        for (int j = 0; j < 8; j++) acc[i][j] = 0.f;

    // A-load mapping: 4 contiguous K per thread
    const int aRow = tid >> 1, aK4 = (tid & 1) * 4;
    // B-load mapping
    const int bR  = BTRANS ? (tid >> 1) : (tid >> 5);        // n-index : k-index
    const int bC4 = BTRANS ? ((tid & 1) * 4) : ((tid & 31) * 4);

    for (int kt = 0; kt < K; kt += 8) {
        {   // A tile -> As[k][m]
            int gm = m0 + aRow;
            float4 v = make_float4(0.f, 0.f, 0.f, 0.f);
            if (gm < M) v = *(const float4*)(A + (size_t)gm * lda + (kt + aK4));
            As[aK4 + 0][aRow] = v.x; As[aK4 + 1][aRow] = v.y;
            As[aK4 + 2][aRow] = v.z; As[aK4 + 3][aRow] = v.w;
        }
        if (BTRANS) {   // B[n, k] -> Bs[k][n]
            int gn = n0 + bR;
            float4 v = make_float4(0.f, 0.f, 0.f, 0.f);
            if (gn < N) v = *(const float4*)(B + (size_t)gn * ldb + (kt + bC4));
            Bs[bC4 + 0][bR] = v.x; Bs[bC4 + 1][bR] = v.y;
            Bs[bC4 + 2][bR] = v.z; Bs[bC4 + 3][bR] = v.w;
        } else {        // B[k, n] -> Bs[k][n]  (N % 4 == 0 so float4 all-in/out)
            int gn = n0 + bC4;
            float4 v = make_float4(0.f, 0.f, 0.f, 0.f);
            if (gn < N) v = *(const float4*)(B + (size_t)(kt + bR) * ldb + gn);
            *(float4*)&Bs[bR][bC4] = v;
        }
        __syncthreads();

#pragma unroll
        for (int k = 0; k < 8; k++) {
            float4 a0 = *(const float4*)&As[k][ty * 8];
            float4 a1 = *(const float4*)&As[k][ty * 8 + 4];
            float4 b0 = *(const float4*)&Bs[k][tx * 8];
            float4 b1 = *(const float4*)&Bs[k][tx * 8 + 4];
            float av[8] = {a0.x, a0.y, a0.z, a0.w, a1.x, a1.y, a1.z, a1.w};
            float bv[8] = {b0.x, b0.y, b0.z, b0.w, b1.x, b1.y, b1.z, b1.w};
#pragma unroll
            for (int i = 0; i < 8; i++)
#pragma unroll
                for (int j = 0; j < 8; j++)
                    acc[i][j] = fmaf(av[i], bv[j], acc[i][j]);
        }
        __syncthreads();
    }

    // Epilogue (col0 % 8 == 0, N % 8 == 0 -> all-in/all-out per thread column strip)
    int col0 = n0 + tx * 8;
    if (col0 < N) {
        float bvals[8];
#pragma unroll
        for (int j = 0; j < 8; j++) bvals[j] = (EPI >= 1) ? bias[col0 + j] : 0.f;
#pragma unroll
        for (int i = 0; i < 8; i++) {
            int row = m0 + ty * 8 + i;
            if (row >= M) continue;
            float o[8];
#pragma unroll
            for (int j = 0; j < 8; j++) {
                float v = acc[i][j] + bvals[j];
                if (EPI == 2) v = mish_f(v);
                o[j] = v;
            }
            float* cp = C + (size_t)row * ldc + col0;
            *(float4*)(cp)     = make_float4(o[0], o[1], o[2], o[3]);
            *(float4*)(cp + 4) = make_float4(o[4], o[5], o[6], o[7]);
        }
    }
}

// ---------------------------------------------------------------------------
// Block reductions
// ---------------------------------------------------------------------------
__device__ __forceinline__ float blkRedSum(float v, float* sm) {
#pragma unroll
    for (int o = 16; o > 0; o >>= 1) v += __shfl_xor_sync(0xffffffffu, v, o);
    int nw = blockDim.x >> 5;
    if ((threadIdx.x & 31) == 0) sm[threadIdx.x >> 5] = v;
    __syncthreads();
    if (threadIdx.x == 0) {
        float s = sm[0];
        for (int i = 1; i < nw; i++) s += sm[i];
        sm[0] = s;
    }
    __syncthreads();
    float r = sm[0];
    __syncthreads();
    return r;
}

__device__ __forceinline__ float blkRedMax(float v, float* sm) {
#pragma unroll
    for (int o = 16; o > 0; o >>= 1) v = fmaxf(v, __shfl_xor_sync(0xffffffffu, v, o));
    int nw = blockDim.x >> 5;
    if ((threadIdx.x & 31) == 0) sm[threadIdx.x >> 5] = v;
    __syncthreads();
    if (threadIdx.x == 0) {
        float s = sm[0];
        for (int i = 1; i < nw; i++) s = fmaxf(s, sm[i]);
        sm[0] = s;
    }
    __syncthreads();
    float r = sm[0];
    __syncthreads();
    return r;
}

// ---------------------------------------------------------------------------
// entmax-1.5 over rows of 1024 (in place). Row = raw q.k dot; z = raw/16
// (1/sqrt(64) attention scale, then /2 from entmax). Bisection + exact
// closed-form refine on the identified support (matches reference formula).
// ---------------------------------------------------------------------------
__global__ __launch_bounds__(256)
void entmax_kernel(float* __restrict__ S)
{
    __shared__ float sm[8];
    float* r = S + (size_t)blockIdx.x * 1024;
    int tid = threadIdx.x;

    float z[4];
#pragma unroll
    for (int j = 0; j < 4; j++) z[j] = r[tid + j * 256] * 0.0625f;

    float m = z[0];
#pragma unroll
    for (int j = 1; j < 4; j++) m = fmaxf(m, z[j]);
    m = blkRedMax(m, sm);
#pragma unroll
    for (int j = 0; j < 4; j++) z[j] -= m;

    // tau in [-1, 0]: f(-1) >= 1 (max element alone contributes 1), f(0) = 0.
    float lo = -1.f, hi = 0.f;
    for (int it = 0; it < 30; it++) {
        float mid = 0.5f * (lo + hi);
        float s = 0.f;
#pragma unroll
        for (int j = 0; j < 4; j++) {
            float d = z[j] - mid;
            if (d > 0.f) s = fmaf(d, d, s);
        }
        s = blkRedSum(s, sm);
        if (s > 1.f) lo = mid; else hi = mid;
    }

    // Closed-form solve on support {z > lo} (identical to reference sort formula)
    float c = 0.f, s1 = 0.f, s2 = 0.f;
#pragma unroll
    for (int j = 0; j < 4; j++) {
        if (z[j] > lo) { c += 1.f; s1 += z[j]; s2 = fmaf(z[j], z[j], s2); }
    }
    c  = blkRedSum(c,  sm);
    s1 = blkRedSum(s1, sm);
    s2 = blkRedSum(s2, sm);
    float disc = fmaxf(s1 * s1 - c * (s2 - 1.f), 0.f);
    float tau = (s1 - sqrtf(disc)) / c;

#pragma unroll
    for (int j = 0; j < 4; j++) {
        float d = fmaxf(z[j] - tau, 0.f);
        r[tid + j * 256] = d * d;
    }
}

// ---------------------------------------------------------------------------
// out = residual + LayerNorm(y) * g + b   (rows of 512, eps = 1e-5, biased var)
// ---------------------------------------------------------------------------
__global__ __launch_bounds__(128)
void add_ln_kernel(const float* __restrict__ Y, const float* __restrict__ R,
                   const float* __restrict__ g, const float* __restrict__ b,
                   float* __restrict__ O)
{
    __shared__ float sm[4];
    size_t row = blockIdx.x;
    const float* y = Y + row * 512;
    int tid = threadIdx.x;

    float v[4];
#pragma unroll
    for (int j = 0; j < 4; j++) v[j] = y[tid + j * 128];
    float s = 0.f, ss = 0.f;
#pragma unroll
    for (int j = 0; j < 4; j++) { s += v[j]; ss = fmaf(v[j], v[j], ss); }
    s  = blkRedSum(s,  sm);
    ss = blkRedSum(ss, sm);
    float mean = s * (1.f / 512.f);
    float var  = ss * (1.f / 512.f) - mean * mean;
    float rstd = rsqrtf(var + 1e-5f);
#pragma unroll
    for (int j = 0; j < 4; j++) {
        int c = tid + j * 128;
        O[row * 512 + c] = R[row * 512 + c] + (v[j] - mean) * rstd * g[c] + b[c];
    }
}

// ---------------------------------------------------------------------------
extern "C" void kernel_launch(void* const* d_in, const int* in_sizes, int n_in,
                              void* d_out, int out_size)
{
    const float* x   = (const float*)d_in[0];
    const float* Wq  = (const float*)d_in[1];  const float* bq  = (const float*)d_in[2];
    const float* Wk  = (const float*)d_in[3];  const float* bk  = (const float*)d_in[4];
    const float* Wv  = (const float*)d_in[5];  const float* bv  = (const float*)d_in[6];
    const float* Wo  = (const float*)d_in[7];  const float* bo  = (const float*)d_in[8];
    const float* g1  = (const float*)d_in[9];  const float* be1 = (const float*)d_in[10];
    const float* W1  = (const float*)d_in[11]; const float* b1  = (const float*)d_in[12];
    const float* W2  = (const float*)d_in[13]; const float* b2  = (const float*)d_in[14];
    const float* g2  = (const float*)d_in[15]; const float* be2 = (const float*)d_in[16];
    float* out = (float*)d_out;

    float *q, *k, *v, *s, *ctx, *y, *x1, *h1, *y2;
    cudaGetSymbolAddress((void**)&q,   gQ);
    cudaGetSymbolAddress((void**)&k,   gK);
    cudaGetSymbolAddress((void**)&v,   gV);
    cudaGetSymbolAddress((void**)&s,   gS);
    cudaGetSymbolAddress((void**)&ctx, gCtx);
    cudaGetSymbolAddress((void**)&y,   gY);
    cudaGetSymbolAddress((void**)&x1,  gX1);
    cudaGetSymbolAddress((void**)&h1,  gH1);
    cudaGetSymbolAddress((void**)&y2,  gY2);

    const long long SD  = (long long)Sn * Dn;    // per-batch stride in [B,S,D]
    const long long SS  = (long long)Sn * Sn;    // per-(b,h) score matrix

    // 1) QKV projections: [8192,512] @ [512,512] + bias
    {
        dim3 grid(Dn / 128, Mtok / 128, 1);
        sgemm<EPI_BIAS, false><<<grid, 256>>>(x, Wq, bq, q, Mtok, Dn, Dn, Dn, Dn, Dn,
                                              0, 0, 0, 0, 0, 0, 1);
        sgemm<EPI_BIAS, false><<<grid, 256>>>(x, Wk, bk, k, Mtok, Dn, Dn, Dn, Dn, Dn,
                                              0, 0, 0, 0, 0, 0, 1);
        sgemm<EPI_BIAS, false><<<grid, 256>>>(x, Wv, bv, v, Mtok, Dn, Dn, Dn, Dn, Dn,
                                              0, 0, 0, 0, 0, 0, 1);
    }

    // 2) scores[b,h] = Q[b,:,h*64:...] @ K^T  (NT, K=64), batched over 64 (b,h)
    {
        dim3 grid(Sn / 128, Sn / 128, Bn * Hn);
        sgemm<EPI_NONE, true><<<grid, 256>>>(q, k, nullptr, s, Sn, Sn, HD, Dn, Dn, Sn,
                                             SD, HD, SD, HD,
                                             (long long)Hn * SS, SS, Hn);
    }

    // 3) entmax-1.5 over every score row (in place)
    entmax_kernel<<<Bn * Hn * Sn, 256>>>(s);

    // 4) ctx[b,:,h*64:...] = attn @ V   (NN, M=1024, N=64, K=1024)
    {
        dim3 grid(1, Sn / 128, Bn * Hn);
        sgemm<EPI_NONE, false><<<grid, 256>>>(s, v, nullptr, ctx, Sn, HD, Sn, Sn, Dn, Dn,
                                              (long long)Hn * SS, SS,
                                              SD, HD, SD, HD, Hn);
    }

    // 5) y = ctx @ Wo + bo
    sgemm<EPI_BIAS, false><<<dim3(Dn / 128, Mtok / 128, 1), 256>>>(
        ctx, Wo, bo, y, Mtok, Dn, Dn, Dn, Dn, Dn, 0, 0, 0, 0, 0, 0, 1);

    // 6) x1 = x + LN(y)
    add_ln_kernel<<<Mtok, 128>>>(y, x, g1, be1, x1);

    // 7) h1 = mish(x1 @ W1 + b1)  [8192,2048]
    sgemm<EPI_MISH, false><<<dim3(Fn / 128, Mtok / 128, 1), 256>>>(
        x1, W1, b1, h1, Mtok, Fn, Dn, Dn, Fn, Fn, 0, 0, 0, 0, 0, 0, 1);

    // 8) y2 = h1 @ W2 + b2  [8192,512]
    sgemm<EPI_BIAS, false><<<dim3(Dn / 128, Mtok / 128, 1), 256>>>(
        h1, W2, b2, y2, Mtok, Dn, Fn, Fn, Dn, Dn, 0, 0, 0, 0, 0, 0, 1);

    // 9) out = x1 + LN(y2)
    add_ln_kernel<<<Mtok, 128>>>(y2, x1, g2, be2, out);
}

// round 2
// speedup vs baseline: 3.4509x; 3.4509x over previous
#include <cuda_runtime.h>
#include <math.h>
#include <stdint.h>

// Problem constants
constexpr int Bn = 8, Sn = 1024, Dn = 512, Hn = 8, HD = 64, Fn = 2048;
constexpr int Mtok = Bn * Sn; // 8192

// Scratch (static device globals; no runtime allocation)
__device__ float gQ [Mtok * Dn];
__device__ float gK [Mtok * Dn];
__device__ float gV [Mtok * Dn];
__device__ float gS [(size_t)Bn * Hn * Sn * Sn];   // 256 MB scores/attn (in place)
__device__ float gCtx[Mtok * Dn];
__device__ float gY [Mtok * Dn];
__device__ float gX1[Mtok * Dn];
__device__ float gH1[(size_t)Mtok * Fn];
__device__ float gY2[Mtok * Dn];

enum { EPI_NONE = 0, EPI_BIAS = 1, EPI_MISH = 2 };

__device__ __forceinline__ float mish_f(float v) {
    float sp = (v > 20.f) ? v : log1pf(expf(v));
    return v * tanhf(sp);
}

__device__ __forceinline__ float to_tf32(float x) {
    float r;
    asm("cvt.rna.tf32.f32 %0, %1;" : "=f"(r) : "f"(x));
    return r;
}

// ---------------------------------------------------------------------------
// tf32 tensor-core GEMM: C = A @ B (+bias)(+mish).
// BTRANS: B stored [N,K] (K contiguous) -> C = A @ B^T.
// Block tile BM x BN, K-tile 16, 256 threads (8 warps), warp tile WM x WN,
// mma.sync.m16n8k8 tf32. Assumes M%BM==0, N%BN==0, K%16==0, 16B-aligned rows.
// Batched over blockIdx.z with (b,h) = (z/Hdiv, z%Hdiv) strides.
// ---------------------------------------------------------------------------
template <int BM, int BN, int WM, int WN, int EPI, bool BTRANS>
__global__ __launch_bounds__(256)
void tgemm(const float* __restrict__ Ag, const float* __restrict__ Bg,
           const float* __restrict__ bias, float* __restrict__ Cg,
           int M, int N, int K, int lda, int ldb, int ldc,
           long long sA_b, long long sA_h,
           long long sB_b, long long sB_h,
           long long sC_b, long long sC_h, int Hdiv)
{
    constexpr int BK = 16;
    constexpr int WARPS_N = BN / WN;
    constexpr int MI = WM / 16;
    constexpr int NI = WN / 8;
    constexpr int ASTR = BK + 4;             // 20: conflict-free frag reads
    constexpr int BNP  = BN + 8;             // for non-trans B [k][n]

    int z  = blockIdx.z;
    int bb = z / Hdiv, hh = z - bb * Hdiv;
    const float* A = Ag + (size_t)bb * sA_b + (size_t)hh * sA_h;
    const float* B = Bg + (size_t)bb * sB_b + (size_t)hh * sB_h;
    float*       C = Cg + (size_t)bb * sC_b + (size_t)hh * sC_h;

    __shared__ __align__(16) float As[BM * ASTR];
    __shared__ __align__(16) float Bs[BTRANS ? BN * ASTR : BK * BNP];

    const int tid  = threadIdx.x;
    const int lane = tid & 31;
    const int w    = tid >> 5;
    const int gid  = lane >> 2;   // 0..7
    const int tig  = lane & 3;    // 0..3
    const int wm0  = (w / WARPS_N) * WM;
    const int wn0  = (w % WARPS_N) * WN;
    const int m0   = blockIdx.y * BM;
    const int n0   = blockIdx.x * BN;

    float acc[MI][NI][4];
#pragma unroll
    for (int i = 0; i < MI; i++)
#pragma unroll
        for (int j = 0; j < NI; j++)
#pragma unroll
            for (int c = 0; c < 4; c++) acc[i][j][c] = 0.f;

    for (int kt = 0; kt < K; kt += BK) {
        // --- A tile: [m][k] -> As[m][ASTR] (tf32) ---
#pragma unroll
        for (int i = tid; i < BM * 4; i += 256) {
            int m = i >> 2, kc = (i & 3) * 4;
            float4 v = *(const float4*)(A + (size_t)(m0 + m) * lda + kt + kc);
            float* p = As + m * ASTR + kc;
            p[0] = to_tf32(v.x); p[1] = to_tf32(v.y);
            p[2] = to_tf32(v.z); p[3] = to_tf32(v.w);
        }
        // --- B tile ---
        if (BTRANS) {
#pragma unroll
            for (int i = tid; i < BN * 4; i += 256) {
                int n = i >> 2, kc = (i & 3) * 4;
                float4 v = *(const float4*)(B + (size_t)(n0 + n) * ldb + kt + kc);
                float* p = Bs + n * ASTR + kc;
                p[0] = to_tf32(v.x); p[1] = to_tf32(v.y);
                p[2] = to_tf32(v.z); p[3] = to_tf32(v.w);
            }
        } else {
#pragma unroll
            for (int i = tid; i < 4 * BN; i += 256) {
                int kr = i / (BN / 4), nq = (i % (BN / 4)) * 4;
                float4 v = *(const float4*)(B + (size_t)(kt + kr) * ldb + n0 + nq);
                float* p = Bs + kr * BNP + nq;
                p[0] = to_tf32(v.x); p[1] = to_tf32(v.y);
                p[2] = to_tf32(v.z); p[3] = to_tf32(v.w);
            }
        }
        __syncthreads();

#pragma unroll
        for (int ks = 0; ks < BK; ks += 8) {
            uint32_t af[MI][4], bf[NI][2];
#pragma unroll
            for (int mi = 0; mi < MI; mi++) {
                const float* ap = As + (wm0 + mi * 16 + gid) * ASTR + ks + tig;
                af[mi][0] = __float_as_uint(ap[0]);
                af[mi][1] = __float_as_uint(ap[8 * ASTR]);
                af[mi][2] = __float_as_uint(ap[4]);
                af[mi][3] = __float_as_uint(ap[8 * ASTR + 4]);
            }
#pragma unroll
            for (int ni = 0; ni < NI; ni++) {
                if (BTRANS) {
                    const float* bp = Bs + (wn0 + ni * 8 + gid) * ASTR + ks + tig;
                    bf[ni][0] = __float_as_uint(bp[0]);
                    bf[ni][1] = __float_as_uint(bp[4]);
                } else {
                    const float* bp = Bs + (ks + tig) * BNP + wn0 + ni * 8 + gid;
                    bf[ni][0] = __float_as_uint(bp[0]);
                    bf[ni][1] = __float_as_uint(bp[4 * BNP]);
                }
            }
#pragma unroll
            for (int mi = 0; mi < MI; mi++)
#pragma unroll
                for (int ni = 0; ni < NI; ni++) {
                    asm volatile(
                        "mma.sync.aligned.m16n8k8.row.col.f32.tf32.tf32.f32 "
                        "{%0,%1,%2,%3}, {%4,%5,%6,%7}, {%8,%9}, {%0,%1,%2,%3};"
                        : "+f"(acc[mi][ni][0]), "+f"(acc[mi][ni][1]),
                          "+f"(acc[mi][ni][2]), "+f"(acc[mi][ni][3])
                        : "r"(af[mi][0]), "r"(af[mi][1]),
                          "r"(af[mi][2]), "r"(af[mi][3]),
                          "r"(bf[ni][0]), "r"(bf[ni][1]));
                }
        }
        __syncthreads();
    }

    // --- Epilogue ---
#pragma unroll
    for (int mi = 0; mi < MI; mi++) {
#pragma unroll
        for (int ni = 0; ni < NI; ni++) {
            int row = m0 + wm0 + mi * 16 + gid;
            int col = n0 + wn0 + ni * 8 + tig * 2;
            float b0 = 0.f, b1 = 0.f;
            if (EPI >= 1) { b0 = bias[col]; b1 = bias[col + 1]; }
            float v0 = acc[mi][ni][0] + b0, v1 = acc[mi][ni][1] + b1;
            float v2 = acc[mi][ni][2] + b0, v3 = acc[mi][ni][3] + b1;
            if (EPI == 2) { v0 = mish_f(v0); v1 = mish_f(v1); v2 = mish_f(v2); v3 = mish_f(v3); }
            *(float2*)(C + (size_t)row * ldc + col)       = make_float2(v0, v1);
            *(float2*)(C + (size_t)(row + 8) * ldc + col) = make_float2(v2, v3);
        }
    }
}

// ---------------------------------------------------------------------------
// entmax-1.5, warp-per-row (rows of 1024, in place). z = raw/16
// (1/sqrt(64) attn scale, /2 entmax). Bisection + closed-form refine on
// identified support (identical formula to reference sorted solve).
// ---------------------------------------------------------------------------
__global__ __launch_bounds__(256)
void entmax_kernel(float* __restrict__ S)
{
    int row  = (blockIdx.x << 3) + (threadIdx.x >> 5);
    int lane = threadIdx.x & 31;
    float4* r = (float4*)(S + (size_t)row * 1024);

    float z[32];
#pragma unroll
    for (int wq = 0; wq < 8; wq++) {
        float4 v = r[wq * 32 + lane];
        z[wq * 4 + 0] = v.x * 0.0625f; z[wq * 4 + 1] = v.y * 0.0625f;
        z[wq * 4 + 2] = v.z * 0.0625f; z[wq * 4 + 3] = v.w * 0.0625f;
    }

    float m = z[0];
#pragma unroll
    for (int j = 1; j < 32; j++) m = fmaxf(m, z[j]);
#pragma unroll
    for (int o = 16; o > 0; o >>= 1) m = fmaxf(m, __shfl_xor_sync(0xffffffffu, m, o));
#pragma unroll
    for (int j = 0; j < 32; j++) z[j] -= m;

    // tau in [-1, 0]: f(-1) >= 1, f(0) = 0 (f monotone decreasing)
    float lo = -1.f, hi = 0.f;
    for (int it = 0; it < 22; it++) {
        float mid = 0.5f * (lo + hi);
        float s = 0.f;
#pragma unroll
        for (int j = 0; j < 32; j++) {
            float d = z[j] - mid;
            if (d > 0.f) s = fmaf(d, d, s);
        }
#pragma unroll
        for (int o = 16; o > 0; o >>= 1) s += __shfl_xor_sync(0xffffffffu, s, o);
        if (s > 1.f) lo = mid; else hi = mid;
    }

    // Closed-form on support {z > lo}: tau = (S1 - sqrt(S1^2 - k(S2-1)))/k
    float c = 0.f, s1 = 0.f, s2 = 0.f;
#pragma unroll
    for (int j = 0; j < 32; j++) {
        if (z[j] > lo) { c += 1.f; s1 += z[j]; s2 = fmaf(z[j], z[j], s2); }
    }
#pragma unroll
    for (int o = 16; o > 0; o >>= 1) {
        c  += __shfl_xor_sync(0xffffffffu, c,  o);
        s1 += __shfl_xor_sync(0xffffffffu, s1, o);
        s2 += __shfl_xor_sync(0xffffffffu, s2, o);
    }
    float disc = fmaxf(s1 * s1 - c * (s2 - 1.f), 0.f);
    float tau  = (s1 - sqrtf(disc)) / c;

#pragma unroll
    for (int wq = 0; wq < 8; wq++) {
        float d0 = fmaxf(z[wq * 4 + 0] - tau, 0.f);
        float d1 = fmaxf(z[wq * 4 + 1] - tau, 0.f);
        float d2 = fmaxf(z[wq * 4 + 2] - tau, 0.f);
        float d3 = fmaxf(z[wq * 4 + 3] - tau, 0.f);
        r[wq * 32 + lane] = make_float4(d0 * d0, d1 * d1, d2 * d2, d3 * d3);
    }
}

// ---------------------------------------------------------------------------
// Block reductions (for LN)
// ---------------------------------------------------------------------------
__device__ __forceinline__ float blkRedSum(float v, float* sm) {
#pragma unroll
    for (int o = 16; o > 0; o >>= 1) v += __shfl_xor_sync(0xffffffffu, v, o);
    int nw = blockDim.x >> 5;
    if ((threadIdx.x & 31) == 0) sm[threadIdx.x >> 5] = v;
    __syncthreads();
    if (threadIdx.x == 0) {
        float s = sm[0];
        for (int i = 1; i < nw; i++) s += sm[i];
        sm[0] = s;
    }
    __syncthreads();
    float r = sm[0];
    __syncthreads();
    return r;
}

// out = residual + LayerNorm(y) * g + b   (rows of 512, eps=1e-5, biased var)
__global__ __launch_bounds__(128)
void add_ln_kernel(const float* __restrict__ Y, const float* __restrict__ R,
                   const float* __restrict__ g, const float* __restrict__ b,
                   float* __restrict__ O)
{
    __shared__ float sm[4];
    size_t row = blockIdx.x;
    const float* y = Y + row * 512;
    int tid = threadIdx.x;

    float v[4];
#pragma unroll
    for (int j = 0; j < 4; j++) v[j] = y[tid + j * 128];
    float s = 0.f, ss = 0.f;
#pragma unroll
    for (int j = 0; j < 4; j++) { s += v[j]; ss = fmaf(v[j], v[j], ss); }
    s  = blkRedSum(s,  sm);
    ss = blkRedSum(ss, sm);
    float mean = s * (1.f / 512.f);
    float var  = ss * (1.f / 512.f) - mean * mean;
    float rstd = rsqrtf(var + 1e-5f);
#pragma unroll
    for (int j = 0; j < 4; j++) {
        int c = tid + j * 128;
        O[row * 512 + c] = R[row * 512 + c] + (v[j] - mean) * rstd * g[c] + b[c];
    }
}

// ---------------------------------------------------------------------------
extern "C" void kernel_launch(void* const* d_in, const int* in_sizes, int n_in,
                              void* d_out, int out_size)
{
    const float* x   = (const float*)d_in[0];
    const float* Wq  = (const float*)d_in[1];  const float* bq  = (const float*)d_in[2];
    const float* Wk  = (const float*)d_in[3];  const float* bk  = (const float*)d_in[4];
    const float* Wv  = (const float*)d_in[5];  const float* bv  = (const float*)d_in[6];
    const float* Wo  = (const float*)d_in[7];  const float* bo  = (const float*)d_in[8];
    const float* g1  = (const float*)d_in[9];  const float* be1 = (const float*)d_in[10];
    const float* W1  = (const float*)d_in[11]; const float* b1  = (const float*)d_in[12];
    const float* W2  = (const float*)d_in[13]; const float* b2  = (const float*)d_in[14];
    const float* g2  = (const float*)d_in[15]; const float* be2 = (const float*)d_in[16];
    float* out = (float*)d_out;

    float *q, *k, *v, *s, *ctx, *y, *x1, *h1, *y2;
    cudaGetSymbolAddress((void**)&q,   gQ);
    cudaGetSymbolAddress((void**)&k,   gK);
    cudaGetSymbolAddress((void**)&v,   gV);
    cudaGetSymbolAddress((void**)&s,   gS);
    cudaGetSymbolAddress((void**)&ctx, gCtx);
    cudaGetSymbolAddress((void**)&y,   gY);
    cudaGetSymbolAddress((void**)&x1,  gX1);
    cudaGetSymbolAddress((void**)&h1,  gH1);
    cudaGetSymbolAddress((void**)&y2,  gY2);

    const long long SD = (long long)Sn * Dn;   // per-batch stride in [B,S,D]
    const long long SS = (long long)Sn * Sn;   // per-(b,h) score matrix

    // 1) QKV projections: [8192,512] @ [512,512] + bias
    {
        dim3 grid(Dn / 128, Mtok / 128, 1);
        tgemm<128,128,64,32,EPI_BIAS,false><<<grid, 256>>>(
            x, Wq, bq, q, Mtok, Dn, Dn, Dn, Dn, Dn, 0,0,0,0,0,0, 1);
        tgemm<128,128,64,32,EPI_BIAS,false><<<grid, 256>>>(
            x, Wk, bk, k, Mtok, Dn, Dn, Dn, Dn, Dn, 0,0,0,0,0,0, 1);
        tgemm<128,128,64,32,EPI_BIAS,false><<<grid, 256>>>(
            x, Wv, bv, v, Mtok, Dn, Dn, Dn, Dn, Dn, 0,0,0,0,0,0, 1);
    }

    // 2) scores[b,h] = Q_h @ K_h^T  (NT, K=64), batched over 64 (b,h)
    {
        dim3 grid(Sn / 128, Sn / 128, Bn * Hn);
        tgemm<128,128,64,32,EPI_NONE,true><<<grid, 256>>>(
            q, k, nullptr, s, Sn, Sn, HD, Dn, Dn, Sn,
            SD, HD, SD, HD, (long long)Hn * SS, SS, Hn);
    }

    // 3) entmax-1.5 over every score row (in place, warp-per-row)
    entmax_kernel<<<Bn * Hn * Sn / 8, 256>>>(s);

    // 4) ctx_h = attn @ V_h   (NN, M=1024, N=64, K=1024)
    {
        dim3 grid(1, Sn / 128, Bn * Hn);
        tgemm<128,64,32,32,EPI_NONE,false><<<grid, 256>>>(
            s, v, nullptr, ctx, Sn, HD, Sn, Sn, Dn, Dn,
            (long long)Hn * SS, SS, SD, HD, SD, HD, Hn);
    }

    // 5) y = ctx @ Wo + bo
    tgemm<128,128,64,32,EPI_BIAS,false><<<dim3(Dn / 128, Mtok / 128, 1), 256>>>(
        ctx, Wo, bo, y, Mtok, Dn, Dn, Dn, Dn, Dn, 0,0,0,0,0,0, 1);

    // 6) x1 = x + LN(y)
    add_ln_kernel<<<Mtok, 128>>>(y, x, g1, be1, x1);

    // 7) h1 = mish(x1 @ W1 + b1)  [8192,2048]
    tgemm<128,128,64,32,EPI_MISH,false><<<dim3(Fn / 128, Mtok / 128, 1), 256>>>(
        x1, W1, b1, h1, Mtok, Fn, Dn, Dn, Fn, Fn, 0,0,0,0,0,0, 1);

    // 8) y2 = h1 @ W2 + b2  [8192,512]
    tgemm<128,128,64,32,EPI_BIAS,false><<<dim3(Dn / 128, Mtok / 128, 1), 256>>>(
        h1, W2, b2, y2, Mtok, Dn, Fn, Fn, Dn, Dn, 0,0,0,0,0,0, 1);

    // 9) out = x1 + LN(y2)
    add_ln_kernel<<<Mtok, 128>>>(y2, x1, g2, be2, out);
}

// round 3
// speedup vs baseline: 3.9525x; 1.1454x over previous
#include <cuda_runtime.h>
#include <math.h>
#include <stdint.h>

// Problem constants
constexpr int Bn = 8, Sn = 1024, Dn = 512, Hn = 8, HD = 64, Fn = 2048;
constexpr int Mtok = Bn * Sn; // 8192
constexpr int D3 = 3 * Dn;    // 1536

// Scratch (static device globals; no runtime allocation)
__device__ float gQKV [(size_t)Mtok * D3];          // packed Q|K|V rows
__device__ float gWcat[Dn * D3];
__device__ float gBcat[D3];
__device__ float gS  [(size_t)Bn * Hn * Sn * Sn];   // 256 MB scores/attn (in place)
__device__ float gCtx[Mtok * Dn];
__device__ float gY  [Mtok * Dn];
__device__ float gX1 [Mtok * Dn];
__device__ float gH1 [(size_t)Mtok * Fn];
__device__ float gY2 [Mtok * Dn];

enum { EPI_NONE = 0, EPI_BIAS = 1, EPI_MISH = 2 };

__device__ __forceinline__ float mish_f(float v) {
    float sp = (v > 20.f) ? v : log1pf(expf(v));
    return v * tanhf(sp);
}

__device__ __forceinline__ float to_tf32(float x) {
    float r;
    asm("cvt.rna.tf32.f32 %0, %1;" : "=f"(r) : "f"(x));
    return r;
}

__device__ __forceinline__ void cpa16(float* smem_dst, const float* gsrc) {
    uint32_t a = (uint32_t)__cvta_generic_to_shared(smem_dst);
    asm volatile("cp.async.cg.shared.global [%0], [%1], 16;" :: "r"(a), "l"(gsrc));
}
__device__ __forceinline__ void cp_commit() {
    asm volatile("cp.async.commit_group;");
}
template <int NN>
__device__ __forceinline__ void cp_wait() {
    asm volatile("cp.async.wait_group %0;" :: "n"(NN));
}

// ---------------------------------------------------------------------------
// tf32 tensor-core GEMM, 2-stage cp.async pipeline: C = A @ B (+bias)(+mish).
// BTRANS: B stored [N,K] (K contiguous) -> C = A @ B^T.
// Block BM x BN, BK=16, 256 threads (8 warps), warp tile WM x WN,
// mma.sync.m16n8k8 tf32 (cvt.rna at fragment load).
// Requires M%BM==0, N%BN==0, K%16==0, rows 16B-aligned.
// Batched over blockIdx.z: (b,h) = (z/Hdiv, z%Hdiv).
// ---------------------------------------------------------------------------
template <int BM, int BN, int WM, int WN, int EPI, bool BTRANS>
__global__ __launch_bounds__(256, 2)
void tgemm(const float* __restrict__ Ag, const float* __restrict__ Bg,
           const float* __restrict__ bias, float* __restrict__ Cg,
           int M, int N, int K, int lda, int ldb, int ldc,
           long long sA_b, long long sA_h,
           long long sB_b, long long sB_h,
           long long sC_b, long long sC_h, int Hdiv)
{
    constexpr int BK = 16;
    constexpr int WARPS_N = BN / WN;
    constexpr int MI = WM / 16;
    constexpr int NI = WN / 8;
    constexpr int ASTR = BK + 4;             // 20
    constexpr int BNP  = BN + 8;
    constexpr int BS_ELEMS = BTRANS ? BN * ASTR : BK * BNP;

    int z  = blockIdx.z;
    int bb = z / Hdiv, hh = z - bb * Hdiv;
    const float* A = Ag + (size_t)bb * sA_b + (size_t)hh * sA_h;
    const float* B = Bg + (size_t)bb * sB_b + (size_t)hh * sB_h;
    float*       C = Cg + (size_t)bb * sC_b + (size_t)hh * sC_h;

    __shared__ __align__(16) float As[2][BM * ASTR];
    __shared__ __align__(16) float Bs[2][BS_ELEMS];

    const int tid  = threadIdx.x;
    const int lane = tid & 31;
    const int w    = tid >> 5;
    const int gid  = lane >> 2;   // 0..7
    const int tig  = lane & 3;    // 0..3
    const int wm0  = (w / WARPS_N) * WM;
    const int wn0  = (w % WARPS_N) * WN;
    const int m0   = blockIdx.y * BM;
    const int n0   = blockIdx.x * BN;

    float acc[MI][NI][4];
#pragma unroll
    for (int i = 0; i < MI; i++)
#pragma unroll
        for (int j = 0; j < NI; j++)
#pragma unroll
            for (int c = 0; c < 4; c++) acc[i][j][c] = 0.f;

    const int nTiles = K / BK;

    // tile loader (raw fp32 via cp.async)
    auto load_tile = [&](int kt, int buf) {
#pragma unroll
        for (int i = tid; i < BM * 4; i += 256) {
            int m = i >> 2, kc = (i & 3) * 4;
            cpa16(&As[buf][m * ASTR + kc],
                  A + (size_t)(m0 + m) * lda + kt * BK + kc);
        }
        if (BTRANS) {
#pragma unroll
            for (int i = tid; i < BN * 4; i += 256) {
                int n = i >> 2, kc = (i & 3) * 4;
                cpa16(&Bs[buf][n * ASTR + kc],
                      B + (size_t)(n0 + n) * ldb + kt * BK + kc);
            }
        } else {
#pragma unroll
            for (int i = tid; i < BK * BN / 4; i += 256) {
                int kr = i / (BN / 4), nq = (i % (BN / 4)) * 4;
                cpa16(&Bs[buf][kr * BNP + nq],
                      B + (size_t)(kt * BK + kr) * ldb + n0 + nq);
            }
        }
        cp_commit();
    };

    load_tile(0, 0);

    for (int kt = 0; kt < nTiles; kt++) {
        int buf = kt & 1;
        if (kt + 1 < nTiles) {
            load_tile(kt + 1, buf ^ 1);
            cp_wait<1>();
        } else {
            cp_wait<0>();
        }
        __syncthreads();

#pragma unroll
        for (int ks = 0; ks < BK; ks += 8) {
            uint32_t af[MI][4], bf[NI][2];
#pragma unroll
            for (int mi = 0; mi < MI; mi++) {
                const float* ap = As[buf] + (wm0 + mi * 16 + gid) * ASTR + ks + tig;
                af[mi][0] = __float_as_uint(to_tf32(ap[0]));
                af[mi][1] = __float_as_uint(to_tf32(ap[8 * ASTR]));
                af[mi][2] = __float_as_uint(to_tf32(ap[4]));
                af[mi][3] = __float_as_uint(to_tf32(ap[8 * ASTR + 4]));
            }
#pragma unroll
            for (int ni = 0; ni < NI; ni++) {
                if (BTRANS) {
                    const float* bp = Bs[buf] + (wn0 + ni * 8 + gid) * ASTR + ks + tig;
                    bf[ni][0] = __float_as_uint(to_tf32(bp[0]));
                    bf[ni][1] = __float_as_uint(to_tf32(bp[4]));
                } else {
                    const float* bp = Bs[buf] + (ks + tig) * BNP + wn0 + ni * 8 + gid;
                    bf[ni][0] = __float_as_uint(to_tf32(bp[0]));
                    bf[ni][1] = __float_as_uint(to_tf32(bp[4 * BNP]));
                }
            }
#pragma unroll
            for (int mi = 0; mi < MI; mi++)
#pragma unroll
                for (int ni = 0; ni < NI; ni++) {
                    asm volatile(
                        "mma.sync.aligned.m16n8k8.row.col.f32.tf32.tf32.f32 "
                        "{%0,%1,%2,%3}, {%4,%5,%6,%7}, {%8,%9}, {%0,%1,%2,%3};"
                        : "+f"(acc[mi][ni][0]), "+f"(acc[mi][ni][1]),
                          "+f"(acc[mi][ni][2]), "+f"(acc[mi][ni][3])
                        : "r"(af[mi][0]), "r"(af[mi][1]),
                          "r"(af[mi][2]), "r"(af[mi][3]),
                          "r"(bf[ni][0]), "r"(bf[ni][1]));
                }
        }
        __syncthreads();
    }

    // --- Epilogue ---
#pragma unroll
    for (int mi = 0; mi < MI; mi++) {
#pragma unroll
        for (int ni = 0; ni < NI; ni++) {
            int row = m0 + wm0 + mi * 16 + gid;
            int col = n0 + wn0 + ni * 8 + tig * 2;
            float b0 = 0.f, b1 = 0.f;
            if (EPI >= 1) { b0 = bias[col]; b1 = bias[col + 1]; }
            float v0 = acc[mi][ni][0] + b0, v1 = acc[mi][ni][1] + b1;
            float v2 = acc[mi][ni][2] + b0, v3 = acc[mi][ni][3] + b1;
            if (EPI == 2) { v0 = mish_f(v0); v1 = mish_f(v1); v2 = mish_f(v2); v3 = mish_f(v3); }
            *(float2*)(C + (size_t)row * ldc + col)       = make_float2(v0, v1);
            *(float2*)(C + (size_t)(row + 8) * ldc + col) = make_float2(v2, v3);
        }
    }
}

// ---------------------------------------------------------------------------
// Pack Wq|Wk|Wv -> gWcat [512][1536], biases -> gBcat [1536]
// ---------------------------------------------------------------------------
__global__ __launch_bounds__(256)
void concat_qkv(const float* __restrict__ Wq, const float* __restrict__ Wk,
                const float* __restrict__ Wv,
                const float* __restrict__ bq, const float* __restrict__ bk,
                const float* __restrict__ bv,
                float* __restrict__ Wcat, float* __restrict__ bcat)
{
    int i = blockIdx.x * 256 + threadIdx.x;
    if (i < Dn * Dn) {
        int k = i >> 9, n = i & 511;
        Wcat[k * D3 + n]            = Wq[i];
        Wcat[k * D3 + Dn + n]       = Wk[i];
        Wcat[k * D3 + 2 * Dn + n]   = Wv[i];
    }
    if (i < Dn) {
        bcat[i]          = bq[i];
        bcat[Dn + i]     = bk[i];
        bcat[2 * Dn + i] = bv[i];
    }
}

// ---------------------------------------------------------------------------
// entmax-1.5, warp-per-row (rows of 1024, in place). z = raw/16.
// Bisection (16 iters) + closed-form refine on identified support.
// ---------------------------------------------------------------------------
__global__ __launch_bounds__(256)
void entmax_kernel(float* __restrict__ S)
{
    int row  = (blockIdx.x << 3) + (threadIdx.x >> 5);
    int lane = threadIdx.x & 31;
    float4* r = (float4*)(S + (size_t)row * 1024);

    float z[32];
#pragma unroll
    for (int wq = 0; wq < 8; wq++) {
        float4 v = r[wq * 32 + lane];
        z[wq * 4 + 0] = v.x * 0.0625f; z[wq * 4 + 1] = v.y * 0.0625f;
        z[wq * 4 + 2] = v.z * 0.0625f; z[wq * 4 + 3] = v.w * 0.0625f;
    }

    float m = z[0];
#pragma unroll
    for (int j = 1; j < 32; j++) m = fmaxf(m, z[j]);
#pragma unroll
    for (int o = 16; o > 0; o >>= 1) m = fmaxf(m, __shfl_xor_sync(0xffffffffu, m, o));
#pragma unroll
    for (int j = 0; j < 32; j++) z[j] -= m;

    // tau in [-1, 0]: f(-1) >= 1, f(0) = 0, f monotone decreasing
    float lo = -1.f, hi = 0.f;
    for (int it = 0; it < 16; it++) {
        float mid = 0.5f * (lo + hi);
        float s = 0.f;
#pragma unroll
        for (int j = 0; j < 32; j++) {
            float d = z[j] - mid;
            if (d > 0.f) s = fmaf(d, d, s);
        }
#pragma unroll
        for (int o = 16; o > 0; o >>= 1) s += __shfl_xor_sync(0xffffffffu, s, o);
        if (s > 1.f) lo = mid; else hi = mid;
    }

    // Closed-form on support {z > lo}: tau = (S1 - sqrt(S1^2 - k(S2-1)))/k
    float c = 0.f, s1 = 0.f, s2 = 0.f;
#pragma unroll
    for (int j = 0; j < 32; j++) {
        if (z[j] > lo) { c += 1.f; s1 += z[j]; s2 = fmaf(z[j], z[j], s2); }
    }
#pragma unroll
    for (int o = 16; o > 0; o >>= 1) {
        c  += __shfl_xor_sync(0xffffffffu, c,  o);
        s1 += __shfl_xor_sync(0xffffffffu, s1, o);
        s2 += __shfl_xor_sync(0xffffffffu, s2, o);
    }
    float disc = fmaxf(s1 * s1 - c * (s2 - 1.f), 0.f);
    float tau  = (s1 - sqrtf(disc)) / c;

#pragma unroll
    for (int wq = 0; wq < 8; wq++) {
        float d0 = fmaxf(z[wq * 4 + 0] - tau, 0.f);
        float d1 = fmaxf(z[wq * 4 + 1] - tau, 0.f);
        float d2 = fmaxf(z[wq * 4 + 2] - tau, 0.f);
        float d3 = fmaxf(z[wq * 4 + 3] - tau, 0.f);
        r[wq * 32 + lane] = make_float4(d0 * d0, d1 * d1, d2 * d2, d3 * d3);
    }
}

// ---------------------------------------------------------------------------
__device__ __forceinline__ float blkRedSum(float v, float* sm) {
#pragma unroll
    for (int o = 16; o > 0; o >>= 1) v += __shfl_xor_sync(0xffffffffu, v, o);
    int nw = blockDim.x >> 5;
    if ((threadIdx.x & 31) == 0) sm[threadIdx.x >> 5] = v;
    __syncthreads();
    if (threadIdx.x == 0) {
        float s = sm[0];
        for (int i = 1; i < nw; i++) s += sm[i];
        sm[0] = s;
    }
    __syncthreads();
    float r = sm[0];
    __syncthreads();
    return r;
}

// out = residual + LayerNorm(y) * g + b   (rows of 512, eps=1e-5, biased var)
__global__ __launch_bounds__(128)
void add_ln_kernel(const float* __restrict__ Y, const float* __restrict__ R,
                   const float* __restrict__ g, const float* __restrict__ b,
                   float* __restrict__ O)
{
    __shared__ float sm[4];
    size_t row = blockIdx.x;
    const float* y = Y + row * 512;
    int tid = threadIdx.x;

    float v[4];
#pragma unroll
    for (int j = 0; j < 4; j++) v[j] = y[tid + j * 128];
    float s = 0.f, ss = 0.f;
#pragma unroll
    for (int j = 0; j < 4; j++) { s += v[j]; ss = fmaf(v[j], v[j], ss); }
    s  = blkRedSum(s,  sm);
    ss = blkRedSum(ss, sm);
    float mean = s * (1.f / 512.f);
    float var  = ss * (1.f / 512.f) - mean * mean;
    float rstd = rsqrtf(var + 1e-5f);
#pragma unroll
    for (int j = 0; j < 4; j++) {
        int c = tid + j * 128;
        O[row * 512 + c] = R[row * 512 + c] + (v[j] - mean) * rstd * g[c] + b[c];
    }
}

// ---------------------------------------------------------------------------
extern "C" void kernel_launch(void* const* d_in, const int* in_sizes, int n_in,
                              void* d_out, int out_size)
{
    const float* x   = (const float*)d_in[0];
    const float* Wq  = (const float*)d_in[1];  const float* bq  = (const float*)d_in[2];
    const float* Wk  = (const float*)d_in[3];  const float* bk  = (const float*)d_in[4];
    const float* Wv  = (const float*)d_in[5];  const float* bv  = (const float*)d_in[6];
    const float* Wo  = (const float*)d_in[7];  const float* bo  = (const float*)d_in[8];
    const float* g1  = (const float*)d_in[9];  const float* be1 = (const float*)d_in[10];
    const float* W1  = (const float*)d_in[11]; const float* b1  = (const float*)d_in[12];
    const float* W2  = (const float*)d_in[13]; const float* b2  = (const float*)d_in[14];
    const float* g2  = (const float*)d_in[15]; const float* be2 = (const float*)d_in[16];
    float* out = (float*)d_out;

    float *qkv, *wcat, *bcat, *s, *ctx, *y, *x1, *h1, *y2;
    cudaGetSymbolAddress((void**)&qkv,  gQKV);
    cudaGetSymbolAddress((void**)&wcat, gWcat);
    cudaGetSymbolAddress((void**)&bcat, gBcat);
    cudaGetSymbolAddress((void**)&s,    gS);
    cudaGetSymbolAddress((void**)&ctx,  gCtx);
    cudaGetSymbolAddress((void**)&y,    gY);
    cudaGetSymbolAddress((void**)&x1,   gX1);
    cudaGetSymbolAddress((void**)&h1,   gH1);
    cudaGetSymbolAddress((void**)&y2,   gY2);

    const long long SD3 = (long long)Sn * D3;  // per-batch stride in packed QKV
    const long long SS  = (long long)Sn * Sn;  // per-(b,h) score matrix
    const long long SD  = (long long)Sn * Dn;

    // 0) pack QKV weights/biases
    concat_qkv<<<(Dn * Dn + 255) / 256, 256>>>(Wq, Wk, Wv, bq, bk, bv, wcat, bcat);

    // 1) QKV in one GEMM: [8192,512] @ [512,1536] + bias -> gQKV
    tgemm<128,128,64,32,EPI_BIAS,false><<<dim3(D3 / 128, Mtok / 128, 1), 256>>>(
        x, wcat, bcat, qkv, Mtok, D3, Dn, Dn, D3, D3, 0,0,0,0,0,0, 1);

    // 2) scores[b,h] = Q_h @ K_h^T (NT, K=64), batched over 64 (b,h)
    tgemm<128,128,64,32,EPI_NONE,true><<<dim3(Sn / 128, Sn / 128, Bn * Hn), 256>>>(
        qkv, qkv + Dn, nullptr, s, Sn, Sn, HD, D3, D3, Sn,
        SD3, HD, SD3, HD, (long long)Hn * SS, SS, Hn);

    // 3) entmax-1.5 over every score row (in place, warp-per-row)
    entmax_kernel<<<Bn * Hn * Sn / 8, 256>>>(s);

    // 4) ctx_h = attn @ V_h   (NN, M=1024, N=64, K=1024)
    tgemm<128,64,32,32,EPI_NONE,false><<<dim3(1, Sn / 128, Bn * Hn), 256>>>(
        s, qkv + 2 * Dn, nullptr, ctx, Sn, HD, Sn, Sn, D3, Dn,
        (long long)Hn * SS, SS, SD3, HD, SD, HD, Hn);

    // 5) y = ctx @ Wo + bo
    tgemm<128,128,64,32,EPI_BIAS,false><<<dim3(Dn / 128, Mtok / 128, 1), 256>>>(
        ctx, Wo, bo, y, Mtok, Dn, Dn, Dn, Dn, Dn, 0,0,0,0,0,0, 1);

    // 6) x1 = x + LN(y)
    add_ln_kernel<<<Mtok, 128>>>(y, x, g1, be1, x1);

    // 7) h1 = mish(x1 @ W1 + b1)  [8192,2048]
    tgemm<128,128,64,32,EPI_MISH,false><<<dim3(Fn / 128, Mtok / 128, 1), 256>>>(
        x1, W1, b1, h1, Mtok, Fn, Dn, Dn, Fn, Fn, 0,0,0,0,0,0, 1);

    // 8) y2 = h1 @ W2 + b2  [8192,512]
    tgemm<128,128,64,32,EPI_BIAS,false><<<dim3(Dn / 128, Mtok / 128, 1), 256>>>(
        h1, W2, b2, y2, Mtok, Dn, Fn, Fn, Dn, Dn, 0,0,0,0,0,0, 1);

    // 9) out = x1 + LN(y2)
    add_ln_kernel<<<Mtok, 128>>>(y2, x1, g2, be2, out);
}

// round 4
// speedup vs baseline: 4.1758x; 1.0565x over previous
#include <cuda_runtime.h>
#include <math.h>
#include <stdint.h>

// Problem constants
constexpr int Bn = 8, Sn = 1024, Dn = 512, Hn = 8, HD = 64, Fn = 2048;
constexpr int Mtok = Bn * Sn; // 8192
constexpr int D3 = 3 * Dn;    // 1536

// Scratch (static device globals; no runtime allocation)
__device__ float gQKV [(size_t)Mtok * D3];          // packed Q|K|V rows
__device__ float gWcat[Dn * D3];
__device__ float gBcat[D3];
__device__ float gS  [(size_t)Bn * Hn * Sn * Sn];   // 256 MB raw scores
__device__ float gTau[Bn * Hn * Sn];                // per-row threshold (m + tau*)
__device__ float gCtx[Mtok * Dn];
__device__ float gY  [Mtok * Dn];
__device__ float gX1 [Mtok * Dn];
__device__ float gH1 [(size_t)Mtok * Fn];
__device__ float gY2 [Mtok * Dn];

enum { EPI_NONE = 0, EPI_BIAS = 1, EPI_MISH = 2 };

__device__ __forceinline__ float mish_f(float v) {
    float sp = (v > 20.f) ? v : log1pf(expf(v));
    return v * tanhf(sp);
}

__device__ __forceinline__ float to_tf32(float x) {
    float r;
    asm("cvt.rna.tf32.f32 %0, %1;" : "=f"(r) : "f"(x));
    return r;
}

__device__ __forceinline__ void cpa16(float* smem_dst, const float* gsrc) {
    uint32_t a = (uint32_t)__cvta_generic_to_shared(smem_dst);
    asm volatile("cp.async.cg.shared.global [%0], [%1], 16;" :: "r"(a), "l"(gsrc));
}
__device__ __forceinline__ void cp_commit() {
    asm volatile("cp.async.commit_group;");
}
template <int NN>
__device__ __forceinline__ void cp_wait() {
    asm volatile("cp.async.wait_group %0;" :: "n"(NN));
}

// Host/device-consistent smem sizing (3-stage pipeline)
constexpr int ASTRc = 20;
constexpr size_t tg_smem_bytes(int BM, int BN, bool BT) {
    int bs = BT ? BN * ASTRc : 16 * (BN + 8);
    return (size_t)(BM * ASTRc + bs) * 3 * sizeof(float);
}

// ---------------------------------------------------------------------------
// tf32 tensor-core GEMM, 3-stage cp.async pipeline: C = A @ B (+bias)(+mish).
// BTRANS: B stored [N,K] (K contiguous) -> C = A @ B^T.
// ENTA:   A element transform p = (max(a*0.0625 - T[row], 0))^2 at fragment
//         load (entmax apply fused into attn@V).
// Block BM x BN, BK=16, 256 threads (8 warps), warp tile WM x WN,
// mma.sync.m16n8k8 tf32. Requires M%BM==0, N%BN==0, K%16==0, nTiles>=2.
// Batched over blockIdx.z: (b,h) = (z/Hdiv, z%Hdiv).
// ---------------------------------------------------------------------------
template <int BM, int BN, int WM, int WN, int EPI, bool BTRANS, bool ENTA>
__global__ __launch_bounds__(256, 2)
void tgemm(const float* __restrict__ Ag, const float* __restrict__ Bg,
           const float* __restrict__ bias, float* __restrict__ Cg,
           const float* __restrict__ tau,
           int M, int N, int K, int lda, int ldb, int ldc,
           long long sA_b, long long sA_h,
           long long sB_b, long long sB_h,
           long long sC_b, long long sC_h, int Hdiv)
{
    constexpr int BK = 16;
    constexpr int WARPS_N = BN / WN;
    constexpr int MI = WM / 16;
    constexpr int NI = WN / 8;
    constexpr int ASTR = ASTRc;              // 20
    constexpr int BNP  = BN + 8;
    constexpr int BS_ELEMS = BTRANS ? BN * ASTR : BK * BNP;

    extern __shared__ __align__(16) float dsm[];
    float* AsBase = dsm;                          // 3 * BM * ASTR
    float* BsBase = dsm + 3 * BM * ASTR;          // 3 * BS_ELEMS

    int z  = blockIdx.z;
    int bb = z / Hdiv, hh = z - bb * Hdiv;
    const float* A = Ag + (size_t)bb * sA_b + (size_t)hh * sA_h;
    const float* B = Bg + (size_t)bb * sB_b + (size_t)hh * sB_h;
    float*       C = Cg + (size_t)bb * sC_b + (size_t)hh * sC_h;

    const int tid  = threadIdx.x;
    const int lane = tid & 31;
    const int w    = tid >> 5;
    const int gid  = lane >> 2;   // 0..7
    const int tig  = lane & 3;    // 0..3
    const int wm0  = (w / WARPS_N) * WM;
    const int wn0  = (w % WARPS_N) * WN;
    const int m0   = blockIdx.y * BM;
    const int n0   = blockIdx.x * BN;

    // per-row -T for ENTA
    float nT[MI][2];
    if (ENTA) {
        const float* taup = tau + (size_t)z * Sn;
#pragma unroll
        for (int mi = 0; mi < MI; mi++) {
            nT[mi][0] = -taup[m0 + wm0 + mi * 16 + gid];
            nT[mi][1] = -taup[m0 + wm0 + mi * 16 + gid + 8];
        }
    }

    float acc[MI][NI][4];
#pragma unroll
    for (int i = 0; i < MI; i++)
#pragma unroll
        for (int j = 0; j < NI; j++)
#pragma unroll
            for (int c = 0; c < 4; c++) acc[i][j][c] = 0.f;

    const int nTiles = K / BK;

    auto load_tile = [&](int kt, int buf) {
        float* As = AsBase + buf * (BM * ASTR);
        float* Bs = BsBase + buf * BS_ELEMS;
#pragma unroll
        for (int i = tid; i < BM * 4; i += 256) {
            int m = i >> 2, kc = (i & 3) * 4;
            cpa16(&As[m * ASTR + kc], A + (size_t)(m0 + m) * lda + kt * BK + kc);
        }
        if (BTRANS) {
#pragma unroll
            for (int i = tid; i < BN * 4; i += 256) {
                int n = i >> 2, kc = (i & 3) * 4;
                cpa16(&Bs[n * ASTR + kc], B + (size_t)(n0 + n) * ldb + kt * BK + kc);
            }
        } else {
#pragma unroll
            for (int i = tid; i < BK * BN / 4; i += 256) {
                int kr = i / (BN / 4), nq = (i % (BN / 4)) * 4;
                cpa16(&Bs[kr * BNP + nq], B + (size_t)(kt * BK + kr) * ldb + n0 + nq);
            }
        }
        cp_commit();
    };

    load_tile(0, 0);
    load_tile(1, 1);

    for (int kt = 0; kt < nTiles; kt++) {
        if (kt + 1 >= nTiles) cp_wait<0>(); else cp_wait<1>();
        __syncthreads();
        if (kt + 2 < nTiles) load_tile(kt + 2, (kt + 2) % 3);

        int buf = kt % 3;
        const float* As = AsBase + buf * (BM * ASTR);
        const float* Bs = BsBase + buf * BS_ELEMS;

#pragma unroll
        for (int ks = 0; ks < BK; ks += 8) {
            uint32_t af[MI][4], bf[NI][2];
#pragma unroll
            for (int mi = 0; mi < MI; mi++) {
                const float* ap = As + (wm0 + mi * 16 + gid) * ASTR + ks + tig;
                if (ENTA) {
                    float p0 = fmaxf(fmaf(ap[0],            0.0625f, nT[mi][0]), 0.f);
                    float p1 = fmaxf(fmaf(ap[8 * ASTR],     0.0625f, nT[mi][1]), 0.f);
                    float p2 = fmaxf(fmaf(ap[4],            0.0625f, nT[mi][0]), 0.f);
                    float p3 = fmaxf(fmaf(ap[8 * ASTR + 4], 0.0625f, nT[mi][1]), 0.f);
                    af[mi][0] = __float_as_uint(to_tf32(p0 * p0));
                    af[mi][1] = __float_as_uint(to_tf32(p1 * p1));
                    af[mi][2] = __float_as_uint(to_tf32(p2 * p2));
                    af[mi][3] = __float_as_uint(to_tf32(p3 * p3));
                } else {
                    af[mi][0] = __float_as_uint(to_tf32(ap[0]));
                    af[mi][1] = __float_as_uint(to_tf32(ap[8 * ASTR]));
                    af[mi][2] = __float_as_uint(to_tf32(ap[4]));
                    af[mi][3] = __float_as_uint(to_tf32(ap[8 * ASTR + 4]));
                }
            }
#pragma unroll
            for (int ni = 0; ni < NI; ni++) {
                if (BTRANS) {
                    const float* bp = Bs + (wn0 + ni * 8 + gid) * ASTR + ks + tig;
                    bf[ni][0] = __float_as_uint(to_tf32(bp[0]));
                    bf[ni][1] = __float_as_uint(to_tf32(bp[4]));
                } else {
                    const float* bp = Bs + (ks + tig) * BNP + wn0 + ni * 8 + gid;
                    bf[ni][0] = __float_as_uint(to_tf32(bp[0]));
                    bf[ni][1] = __float_as_uint(to_tf32(bp[4 * BNP]));
                }
            }
#pragma unroll
            for (int mi = 0; mi < MI; mi++)
#pragma unroll
                for (int ni = 0; ni < NI; ni++) {
                    asm volatile(
                        "mma.sync.aligned.m16n8k8.row.col.f32.tf32.tf32.f32 "
                        "{%0,%1,%2,%3}, {%4,%5,%6,%7}, {%8,%9}, {%0,%1,%2,%3};"
                        : "+f"(acc[mi][ni][0]), "+f"(acc[mi][ni][1]),
                          "+f"(acc[mi][ni][2]), "+f"(acc[mi][ni][3])
                        : "r"(af[mi][0]), "r"(af[mi][1]),
                          "r"(af[mi][2]), "r"(af[mi][3]),
                          "r"(bf[ni][0]), "r"(bf[ni][1]));
                }
        }
    }

    // --- Epilogue ---
#pragma unroll
    for (int mi = 0; mi < MI; mi++) {
#pragma unroll
        for (int ni = 0; ni < NI; ni++) {
            int row = m0 + wm0 + mi * 16 + gid;
            int col = n0 + wn0 + ni * 8 + tig * 2;
            float b0 = 0.f, b1 = 0.f;
            if (EPI >= 1) { b0 = bias[col]; b1 = bias[col + 1]; }
            float v0 = acc[mi][ni][0] + b0, v1 = acc[mi][ni][1] + b1;
            float v2 = acc[mi][ni][2] + b0, v3 = acc[mi][ni][3] + b1;
            if (EPI == 2) { v0 = mish_f(v0); v1 = mish_f(v1); v2 = mish_f(v2); v3 = mish_f(v3); }
            *(float2*)(C + (size_t)row * ldc + col)       = make_float2(v0, v1);
            *(float2*)(C + (size_t)(row + 8) * ldc + col) = make_float2(v2, v3);
        }
    }
}

// ---------------------------------------------------------------------------
// Pack Wq|Wk|Wv -> gWcat [512][1536], biases -> gBcat [1536]
// ---------------------------------------------------------------------------
__global__ __launch_bounds__(256)
void concat_qkv(const float* __restrict__ Wq, const float* __restrict__ Wk,
                const float* __restrict__ Wv,
                const float* __restrict__ bq, const float* __restrict__ bk,
                const float* __restrict__ bv,
                float* __restrict__ Wcat, float* __restrict__ bcat)
{
    int i = blockIdx.x * 256 + threadIdx.x;
    if (i < Dn * Dn) {
        int k = i >> 9, n = i & 511;
        Wcat[k * D3 + n]          = Wq[i];
        Wcat[k * D3 + Dn + n]     = Wk[i];
        Wcat[k * D3 + 2 * Dn + n] = Wv[i];
    }
    if (i < Dn) {
        bcat[i]          = bq[i];
        bcat[Dn + i]     = bk[i];
        bcat[2 * Dn + i] = bv[i];
    }
}

// ---------------------------------------------------------------------------
// entmax-1.5 tau solve, warp-per-row. Reads raw scores; writes T = m + tau*.
// z = raw/16. 5 bisections + 4 Newton (f convex decreasing: Newton from left
// bracket stays left, converges quadratically) + exact closed-form on support.
// ---------------------------------------------------------------------------
__global__ __launch_bounds__(256)
void entmax_tau_kernel(const float* __restrict__ S, float* __restrict__ Tau)
{
    int row  = (blockIdx.x << 3) + (threadIdx.x >> 5);
    int lane = threadIdx.x & 31;
    const float4* r = (const float4*)(S + (size_t)row * 1024);

    float z[32];
#pragma unroll
    for (int wq = 0; wq < 8; wq++) {
        float4 v = r[wq * 32 + lane];
        z[wq * 4 + 0] = v.x * 0.0625f; z[wq * 4 + 1] = v.y * 0.0625f;
        z[wq * 4 + 2] = v.z * 0.0625f; z[wq * 4 + 3] = v.w * 0.0625f;
    }

    float m = z[0];
#pragma unroll
    for (int j = 1; j < 32; j++) m = fmaxf(m, z[j]);
#pragma unroll
    for (int o = 16; o > 0; o >>= 1) m = fmaxf(m, __shfl_xor_sync(0xffffffffu, m, o));
#pragma unroll
    for (int j = 0; j < 32; j++) z[j] -= m;

    // Bisection: tau* in [-1, 0], f(lo) >= 1 invariant
    float lo = -1.f, hi = 0.f;
#pragma unroll
    for (int it = 0; it < 5; it++) {
        float mid = 0.5f * (lo + hi);
        float s = 0.f;
#pragma unroll
        for (int j = 0; j < 32; j++) {
            float d = fmaxf(z[j] - mid, 0.f);
            s = fmaf(d, d, s);
        }
#pragma unroll
        for (int o = 16; o > 0; o >>= 1) s += __shfl_xor_sync(0xffffffffu, s, o);
        if (s > 1.f) lo = mid; else hi = mid;
    }

    // Newton from the left bracket: tau <- tau + (f-1)/(2*S1)
    float t = lo;
#pragma unroll
    for (int it = 0; it < 4; it++) {
        float s1 = 0.f, s2 = 0.f;
#pragma unroll
        for (int j = 0; j < 32; j++) {
            float d = fmaxf(z[j] - t, 0.f);
            s1 += d;
            s2 = fmaf(d, d, s2);
        }
#pragma unroll
        for (int o = 16; o > 0; o >>= 1) {
            s1 += __shfl_xor_sync(0xffffffffu, s1, o);
            s2 += __shfl_xor_sync(0xffffffffu, s2, o);
        }
        t += (s2 - 1.f) / (2.f * s1);
    }

    // Exact closed-form on support {z > t} (t <= tau*):
    // tau* = (S1 - sqrt(S1^2 - k(S2-1)))/k
    float c = 0.f, s1 = 0.f, s2 = 0.f;
#pragma unroll
    for (int j = 0; j < 32; j++) {
        if (z[j] > t) { c += 1.f; s1 += z[j]; s2 = fmaf(z[j], z[j], s2); }
    }
#pragma unroll
    for (int o = 16; o > 0; o >>= 1) {
        c  += __shfl_xor_sync(0xffffffffu, c,  o);
        s1 += __shfl_xor_sync(0xffffffffu, s1, o);
        s2 += __shfl_xor_sync(0xffffffffu, s2, o);
    }
    float disc = fmaxf(s1 * s1 - c * (s2 - 1.f), 0.f);
    float tau  = (s1 - sqrtf(disc)) / c;

    if (lane == 0) Tau[row] = m + tau;
}

// ---------------------------------------------------------------------------
__device__ __forceinline__ float blkRedSum(float v, float* sm) {
#pragma unroll
    for (int o = 16; o > 0; o >>= 1) v += __shfl_xor_sync(0xffffffffu, v, o);
    int nw = blockDim.x >> 5;
    if ((threadIdx.x & 31) == 0) sm[threadIdx.x >> 5] = v;
    __syncthreads();
    if (threadIdx.x == 0) {
        float s = sm[0];
        for (int i = 1; i < nw; i++) s += sm[i];
        sm[0] = s;
    }
    __syncthreads();
    float r = sm[0];
    __syncthreads();
    return r;
}

// out = residual + LayerNorm(y) * g + b   (rows of 512, eps=1e-5, biased var)
__global__ __launch_bounds__(128)
void add_ln_kernel(const float* __restrict__ Y, const float* __restrict__ R,
                   const float* __restrict__ g, const float* __restrict__ b,
                   float* __restrict__ O)
{
    __shared__ float sm[4];
    size_t row = blockIdx.x;
    const float* y = Y + row * 512;
    int tid = threadIdx.x;

    float v[4];
#pragma unroll
    for (int j = 0; j < 4; j++) v[j] = y[tid + j * 128];
    float s = 0.f, ss = 0.f;
#pragma unroll
    for (int j = 0; j < 4; j++) { s += v[j]; ss = fmaf(v[j], v[j], ss); }
    s  = blkRedSum(s,  sm);
    ss = blkRedSum(ss, sm);
    float mean = s * (1.f / 512.f);
    float var  = ss * (1.f / 512.f) - mean * mean;
    float rstd = rsqrtf(var + 1e-5f);
#pragma unroll
    for (int j = 0; j < 4; j++) {
        int c = tid + j * 128;
        O[row * 512 + c] = R[row * 512 + c] + (v[j] - mean) * rstd * g[c] + b[c];
    }
}

// ---------------------------------------------------------------------------
extern "C" void kernel_launch(void* const* d_in, const int* in_sizes, int n_in,
                              void* d_out, int out_size)
{
    const float* x   = (const float*)d_in[0];
    const float* Wq  = (const float*)d_in[1];  const float* bq  = (const float*)d_in[2];
    const float* Wk  = (const float*)d_in[3];  const float* bk  = (const float*)d_in[4];
    const float* Wv  = (const float*)d_in[5];  const float* bv  = (const float*)d_in[6];
    const float* Wo  = (const float*)d_in[7];  const float* bo  = (const float*)d_in[8];
    const float* g1  = (const float*)d_in[9];  const float* be1 = (const float*)d_in[10];
    const float* W1  = (const float*)d_in[11]; const float* b1  = (const float*)d_in[12];
    const float* W2  = (const float*)d_in[13]; const float* b2  = (const float*)d_in[14];
    const float* g2  = (const float*)d_in[15]; const float* be2 = (const float*)d_in[16];
    float* out = (float*)d_out;

    float *qkv, *wcat, *bcat, *s, *taub, *ctx, *y, *x1, *h1, *y2;
    cudaGetSymbolAddress((void**)&qkv,  gQKV);
    cudaGetSymbolAddress((void**)&wcat, gWcat);
    cudaGetSymbolAddress((void**)&bcat, gBcat);
    cudaGetSymbolAddress((void**)&s,    gS);
    cudaGetSymbolAddress((void**)&taub, gTau);
    cudaGetSymbolAddress((void**)&ctx,  gCtx);
    cudaGetSymbolAddress((void**)&y,    gY);
    cudaGetSymbolAddress((void**)&x1,   gX1);
    cudaGetSymbolAddress((void**)&h1,   gH1);
    cudaGetSymbolAddress((void**)&y2,   gY2);

    const long long SD3 = (long long)Sn * D3;
    const long long SS  = (long long)Sn * Sn;
    const long long SD  = (long long)Sn * Dn;

    // Opt in to >48KB dynamic smem for each instantiation (host-side, cheap)
    constexpr size_t SM_BIG  = tg_smem_bytes(128, 128, false);
    constexpr size_t SM_BIGT = tg_smem_bytes(128, 128, true);
    constexpr size_t SM_ATT  = tg_smem_bytes(128, 64,  false);
    cudaFuncSetAttribute((const void*)tgemm<128,128,64,32,EPI_BIAS,false,false>,
                         cudaFuncAttributeMaxDynamicSharedMemorySize, (int)SM_BIG);
    cudaFuncSetAttribute((const void*)tgemm<128,128,64,32,EPI_NONE,true,false>,
                         cudaFuncAttributeMaxDynamicSharedMemorySize, (int)SM_BIGT);
    cudaFuncSetAttribute((const void*)tgemm<128,64,32,32,EPI_NONE,false,true>,
                         cudaFuncAttributeMaxDynamicSharedMemorySize, (int)SM_ATT);
    cudaFuncSetAttribute((const void*)tgemm<128,128,64,32,EPI_MISH,false,false>,
                         cudaFuncAttributeMaxDynamicSharedMemorySize, (int)SM_BIG);

    // 0) pack QKV weights/biases
    concat_qkv<<<(Dn * Dn + 255) / 256, 256>>>(Wq, Wk, Wv, bq, bk, bv, wcat, bcat);

    // 1) QKV in one GEMM: [8192,512] @ [512,1536] + bias -> gQKV
    tgemm<128,128,64,32,EPI_BIAS,false,false>
        <<<dim3(D3 / 128, Mtok / 128, 1), 256, SM_BIG>>>(
        x, wcat, bcat, qkv, nullptr, Mtok, D3, Dn, Dn, D3, D3, 0,0,0,0,0,0, 1);

    // 2) scores[b,h] = Q_h @ K_h^T (NT, K=64), batched over 64 (b,h)
    tgemm<128,128,64,32,EPI_NONE,true,false>
        <<<dim3(Sn / 128, Sn / 128, Bn * Hn), 256, SM_BIGT>>>(
        qkv, qkv + Dn, nullptr, s, nullptr, Sn, Sn, HD, D3, D3, Sn,
        SD3, HD, SD3, HD, (long long)Hn * SS, SS, Hn);

    // 3) entmax-1.5 tau per score row -> gTau (no score writeback)
    entmax_tau_kernel<<<Bn * Hn * Sn / 8, 256>>>(s, taub);

    // 4) ctx_h = entmax(scores) @ V_h with fused apply (NN, M=1024, N=64, K=1024)
    tgemm<128,64,32,32,EPI_NONE,false,true>
        <<<dim3(1, Sn / 128, Bn * Hn), 256, SM_ATT>>>(
        s, qkv + 2 * Dn, nullptr, ctx, taub, Sn, HD, Sn, Sn, D3, Dn,
        (long long)Hn * SS, SS, SD3, HD, SD, HD, Hn);

    // 5) y = ctx @ Wo + bo
    tgemm<128,128,64,32,EPI_BIAS,false,false>
        <<<dim3(Dn / 128, Mtok / 128, 1), 256, SM_BIG>>>(
        ctx, Wo, bo, y, nullptr, Mtok, Dn, Dn, Dn, Dn, Dn, 0,0,0,0,0,0, 1);

    // 6) x1 = x + LN(y)
    add_ln_kernel<<<Mtok, 128>>>(y, x, g1, be1, x1);

    // 7) h1 = mish(x1 @ W1 + b1)  [8192,2048]
    tgemm<128,128,64,32,EPI_MISH,false,false>
        <<<dim3(Fn / 128, Mtok / 128, 1), 256, SM_BIG>>>(
        x1, W1, b1, h1, nullptr, Mtok, Fn, Dn, Dn, Fn, Fn, 0,0,0,0,0,0, 1);

    // 8) y2 = h1 @ W2 + b2  [8192,512]
    tgemm<128,128,64,32,EPI_BIAS,false,false>
        <<<dim3(Dn / 128, Mtok / 128, 1), 256, SM_BIG>>>(
        h1, W2, b2, y2, nullptr, Mtok, Dn, Fn, Fn, Dn, Dn, 0,0,0,0,0,0, 1);

    // 9) out = x1 + LN(y2)
    add_ln_kernel<<<Mtok, 128>>>(y2, x1, g2, be2, out);
}